// round 14
// baseline (speedup 1.0000x reference)
#include <cuda_runtime.h>

// Problem constants (fixed by setup_inputs)
#define B_ 16
#define T_ 8192
#define D_ 64
#define D2 (D_ / 2)       // 32 float2 columns
#define CHUNK 16          // == WINDOW
#define CPT 2             // chunks per thread -> 32 timesteps per thread
#define TPT (CHUNK * CPT) // 32
#define YDIM 4
#define BLOCK_T (TPT * YDIM) // 128 timesteps per block

__device__ __forceinline__ float fexp2(float x) {
    float y; asm("ex2.approx.ftz.f32 %0, %1;" : "=f"(y) : "f"(x)); return y;
}
__device__ __forceinline__ float flog2(float x) {
    float y; asm("lg2.approx.ftz.f32 %0, %1;" : "=f"(y) : "f"(x)); return y;
}

// out[b,t,d] = -(1/5) * log( sum_{k=0..15} exp(-5 * x[b, max(t-k,0), d]) )
// Chunked prefix/suffix decomposition, float2 over D, streaming stores,
// in-place suffix construction (R13 frame: 2048 x 128-thr, CPT=2).
// R14: the warp ceiling is the REGISTER FILE (64 regs x 32 warps = full RF).
// Loads split into two 8-deep batches (one v[8] buffer) cuts the live set
// to ~54 regs; launch_bounds(128,9) -> 56-reg cap -> 36 resident warps/SM.
__global__ __launch_bounds__(128, 9) void always_kernel(
    const float* __restrict__ lower,
    const float* __restrict__ upper,
    float* __restrict__ out)
{
    const float C1 = -7.2134752044448169f;   // -5 * log2(e)
    const float C2 = -0.13862943611198906f;  // -ln(2) / 5

    const int d2 = threadIdx.x;              // 0..31 float2 column (coalesced)
    const int b  = blockIdx.y;               // 0..15
    const int tr = blockIdx.z;               // 0: lower, 1: upper
    const int t0 = blockIdx.x * BLOCK_T + threadIdx.y * TPT;

    const float* src = tr ? upper : lower;
    float*       dst = out + (size_t)tr * ((size_t)B_ * T_ * D_);

    const float2* col  = (const float2*)src + (size_t)b * T_ * D2 + d2;
    float2*       ocol = (float2*)dst      + (size_t)b * T_ * D2 + d2;

    // Halo suffix sums of the 15 preceding (index-clamped) timesteps.
    // Clamp to 0 reproduces h0's replication of x[:,0,:] exactly
    // (duplicates ARE counted in the logsumexp, matching the reference).
    float sfx[16], sfy[16];                  // slots 1..15 used
    {
        float2 vh[8];
        // batch 1: k = 1..8
        #pragma unroll
        for (int k = 1; k <= 8; k++) {
            int t = t0 - 16 + k;
            if (t < 0) t = 0;
            vh[k - 1] = col[t * D2];
        }
        #pragma unroll
        for (int k = 1; k <= 8; k++) {
            sfx[k] = fexp2(vh[k - 1].x * C1);
            sfy[k] = fexp2(vh[k - 1].y * C1);
        }
        // batch 2: k = 9..15
        #pragma unroll
        for (int k = 9; k < 16; k++) {
            int t = t0 - 16 + k;
            if (t < 0) t = 0;
            vh[k - 9] = col[t * D2];
        }
        #pragma unroll
        for (int k = 9; k < 16; k++) {
            sfx[k] = fexp2(vh[k - 9].x * C1);
            sfy[k] = fexp2(vh[k - 9].y * C1);
        }
        #pragma unroll
        for (int k = 14; k >= 1; k--) { sfx[k] += sfx[k + 1]; sfy[k] += sfy[k + 1]; }
    }

    #pragma unroll 1
    for (int c = 0; c < CPT; c++) {
        const int tc = t0 + c * CHUNK;
        float2 v[8];
        float px = 0.0f, py = 0.0f;

        // ---- half 1: rows 0..7 ----
        #pragma unroll
        for (int r = 0; r < 8; r++) v[r] = col[(tc + r) * D2];
        #pragma unroll
        for (int r = 0; r < 8; r++) {
            float ex = fexp2(v[r].x * C1);
            float ey = fexp2(v[r].y * C1);
            px += ex;
            py += ey;
            float wx = px + sfx[r + 1];
            float wy = py + sfy[r + 1];
            float2 o;
            o.x = flog2(wx) * C2;
            o.y = flog2(wy) * C2;
            __stcs(&ocol[(tc + r) * D2], o);   // evict-first: outputs never re-read
            if (r >= 1) { sfx[r] = ex; sfy[r] = ey; }  // in-place: sf[r] dead after r-1
        }

        // ---- half 2: rows 8..15 ----
        #pragma unroll
        for (int r = 0; r < 8; r++) v[r] = col[(tc + 8 + r) * D2];
        #pragma unroll
        for (int r = 8; r < 16; r++) {
            float ex = fexp2(v[r - 8].x * C1);
            float ey = fexp2(v[r - 8].y * C1);
            px += ex;
            py += ey;
            float wx = (r < 15) ? (px + sfx[r + 1]) : px;
            float wy = (r < 15) ? (py + sfy[r + 1]) : py;
            float2 o;
            o.x = flog2(wx) * C2;
            o.y = flog2(wy) * C2;
            __stcs(&ocol[(tc + r) * D2], o);
            sfx[r] = ex; sfy[r] = ey;
        }

        // Reverse-accumulate in place -> suffix sums for the next chunk.
        if (c + 1 < CPT) {
            #pragma unroll
            for (int k = 14; k >= 1; k--) { sfx[k] += sfx[k + 1]; sfy[k] += sfy[k + 1]; }
        }
    }
}

extern "C" void kernel_launch(void* const* d_in, const int* in_sizes, int n_in,
                              void* d_out, int out_size) {
    const float* lower = (const float*)d_in[0];
    const float* upper = (const float*)d_in[1];
    float* out = (float*)d_out;

    dim3 block(D2, YDIM);                  // 32 x 4 = 128 threads
    dim3 grid(T_ / BLOCK_T, B_, 2);        // 64 x 16 x 2 = 2048 blocks
    always_kernel<<<grid, block>>>(lower, upper, out);
}

// round 15
// speedup vs baseline: 1.0247x; 1.0247x over previous
#include <cuda_runtime.h>

// Problem constants (fixed by setup_inputs)
#define B_ 16
#define T_ 8192
#define D_ 64
#define D2 (D_ / 2)       // 32 float2 columns
#define CHUNK 16          // == WINDOW
#define CPT 2             // chunks per thread -> 32 timesteps per thread
#define TPT (CHUNK * CPT) // 32
#define YDIM 4
#define BLOCK_T (TPT * YDIM) // 128 timesteps per block

__device__ __forceinline__ float fexp2(float x) {
    float y; asm("ex2.approx.ftz.f32 %0, %1;" : "=f"(y) : "f"(x)); return y;
}
__device__ __forceinline__ float flog2(float x) {
    float y; asm("lg2.approx.ftz.f32 %0, %1;" : "=f"(y) : "f"(x)); return y;
}

// out[b,t,d] = -(1/5) * log( sum_{k=0..15} exp(-5 * x[b, max(t-k,0), d]) )
// FINAL (R13 config, measured best: 20.54us harness / 19.39us ncu).
// - Chunked prefix/suffix decomposition: window [t-15,t] spans <=2 aligned
//   16-chunks; window_sum = prefix_cur[r] + suffix_prev[r+1]. Fully
//   parallel, numerically exact vs the reference scan (rel_err 7e-8).
// - float2 over D: LDG.64/STG.64, fully coalesced (256B/warp/slot).
// - __stcs streaming stores: outputs never re-read -> evict-first keeps L2
//   for input halo re-reads (measured win in R6).
// - In-place suffix construction: e[r] overwrites sf[r] the step after
//   sf[r] dies -> live set fits 64 regs.
// - 2048 x 128-thread blocks, CPT=2: 55 warps/SM offered, 64-reg RF cap
//   admits ~27-32 resident -> the measured optimum (R14 proved more warps
//   at shallower MLP is worse; R7/R9/R12 proved fewer warps at deeper MLP
//   is worse).
__global__ __launch_bounds__(128, 8) void always_kernel(
    const float* __restrict__ lower,
    const float* __restrict__ upper,
    float* __restrict__ out)
{
    const float C1 = -7.2134752044448169f;   // -5 * log2(e)
    const float C2 = -0.13862943611198906f;  // -ln(2) / 5

    const int d2 = threadIdx.x;              // 0..31 float2 column (coalesced)
    const int b  = blockIdx.y;               // 0..15
    const int tr = blockIdx.z;               // 0: lower, 1: upper
    const int t0 = blockIdx.x * BLOCK_T + threadIdx.y * TPT;

    const float* src = tr ? upper : lower;
    float*       dst = out + (size_t)tr * ((size_t)B_ * T_ * D_);

    const float2* col  = (const float2*)src + (size_t)b * T_ * D2 + d2;
    float2*       ocol = (float2*)dst      + (size_t)b * T_ * D2 + d2;

    // Halo suffix sums of the 15 preceding (index-clamped) timesteps.
    // Clamp to 0 reproduces h0's replication of x[:,0,:] exactly
    // (duplicates ARE counted in the logsumexp, matching the reference).
    float sfx[16], sfy[16];                  // slots 1..15 used
    {
        float2 vh[16];
        #pragma unroll
        for (int k = 1; k < 16; k++) {
            int t = t0 - 16 + k;
            if (t < 0) t = 0;
            vh[k] = col[t * D2];
        }
        #pragma unroll
        for (int k = 1; k < 16; k++) {
            sfx[k] = fexp2(vh[k].x * C1);
            sfy[k] = fexp2(vh[k].y * C1);
        }
        #pragma unroll
        for (int k = 14; k >= 1; k--) { sfx[k] += sfx[k + 1]; sfy[k] += sfy[k + 1]; }
    }

    #pragma unroll 1
    for (int c = 0; c < CPT; c++) {
        const int tc = t0 + c * CHUNK;

        // 16 independent LDG.64 -> 16-deep MLP per warp (the measured
        // optimum depth), 256B per warp per issue slot.
        float2 v[16];
        #pragma unroll
        for (int r = 0; r < 16; r++) v[r] = col[(tc + r) * D2];

        // Fused pass: window_sum = prefix_cur[r] + suffix_prev[r+1].
        // e[r] is written into sf[r] IN PLACE: sf[r] was last read at step
        // r-1, so the slot is dead by the time step r overwrites it.
        float px = 0.0f, py = 0.0f;
        #pragma unroll
        for (int r = 0; r < 16; r++) {
            float ex = fexp2(v[r].x * C1);
            float ey = fexp2(v[r].y * C1);
            px += ex;
            py += ey;
            float wx = (r < 15) ? (px + sfx[r + 1]) : px;
            float wy = (r < 15) ? (py + sfy[r + 1]) : py;
            float2 o;
            o.x = flog2(wx) * C2;
            o.y = flog2(wy) * C2;
            __stcs(&ocol[(tc + r) * D2], o);   // evict-first: outputs never re-read
            if (r >= 1) { sfx[r] = ex; sfy[r] = ey; }  // e[0] never needed again
        }

        // Reverse-accumulate in place -> suffix sums for the next chunk.
        if (c + 1 < CPT) {
            #pragma unroll
            for (int k = 14; k >= 1; k--) { sfx[k] += sfx[k + 1]; sfy[k] += sfy[k + 1]; }
        }
    }
}

extern "C" void kernel_launch(void* const* d_in, const int* in_sizes, int n_in,
                              void* d_out, int out_size) {
    const float* lower = (const float*)d_in[0];
    const float* upper = (const float*)d_in[1];
    float* out = (float*)d_out;

    dim3 block(D2, YDIM);                  // 32 x 4 = 128 threads
    dim3 grid(T_ / BLOCK_T, B_, 2);        // 64 x 16 x 2 = 2048 blocks
    always_kernel<<<grid, block>>>(lower, upper, out);
}